// round 1
// baseline (speedup 1.0000x reference)
#include <cuda_runtime.h>
#include <math.h>

#define NTOK 8192
#define DIN  1024
#define NEXP 8
#define HID  4096
#define OUTD 1024
#define GH   4096   // gate hidden = 4*D

// ---------------- scratch (device globals; no runtime allocation) ----------------
__device__ float g_h1 [(size_t)NTOK * GH];          // 128 MB
__device__ float g_h2 [(size_t)NTOK * DIN];         // 32 MB
__device__ float g_hid [(size_t)NEXP * NTOK * HID]; // 1 GB   (per-pair hidden)
__device__ float g_pout[(size_t)NEXP * NTOK * OUTD];// 256 MB (per-pair expert out)
__device__ int   g_cnt [NEXP];
__device__ int   g_list[NEXP * NTOK];
__device__ int   g_slot[NTOK * 2];
__device__ float g_wt  [NTOK * 2];

// ---------------- reset per-replay state ----------------
__global__ void reset_kernel() {
    if (threadIdx.x < NEXP) g_cnt[threadIdx.x] = 0;
}

// ---------------- generic fp32 SGEMM 128x128x8, C = (A@B + bias) [relu] ----------------
// A: [M x K] row-major (M = gridDim.y*128, exact), B: [K x N] row-major.
__global__ __launch_bounds__(256) void sgemm_gate(
    const float* __restrict__ A, const float* __restrict__ B,
    const float* __restrict__ bias, float* __restrict__ C,
    int N, int K, int doRelu)
{
    __shared__ float As[8][128];
    __shared__ float Bs[8][128];
    const int tid = threadIdx.x;
    const int m0 = blockIdx.y * 128;
    const int n0 = blockIdx.x * 128;
    const int arow = tid >> 1, acol = (tid & 1) * 4;
    const int brow = tid >> 5, bcol = (tid & 31) * 4;
    const int tx = (tid & 15) * 8, ty = (tid >> 4) * 8;

    float acc[8][8];
    #pragma unroll
    for (int i = 0; i < 8; i++)
        #pragma unroll
        for (int j = 0; j < 8; j++) acc[i][j] = 0.f;

    const float* Ag = A + (size_t)(m0 + arow) * K + acol;
    const float* Bg = B + (size_t)brow * N + n0 + bcol;

    for (int k0 = 0; k0 < K; k0 += 8) {
        float4 av = *(const float4*)(Ag + k0);
        float4 bv = *(const float4*)(Bg + (size_t)k0 * N);
        As[acol + 0][arow] = av.x;
        As[acol + 1][arow] = av.y;
        As[acol + 2][arow] = av.z;
        As[acol + 3][arow] = av.w;
        *(float4*)&Bs[brow][bcol] = bv;
        __syncthreads();
        #pragma unroll
        for (int k = 0; k < 8; k++) {
            float4 a0 = *(float4*)&As[k][ty];
            float4 a1 = *(float4*)&As[k][ty + 4];
            float4 b0 = *(float4*)&Bs[k][tx];
            float4 b1 = *(float4*)&Bs[k][tx + 4];
            float a[8] = {a0.x,a0.y,a0.z,a0.w,a1.x,a1.y,a1.z,a1.w};
            float b[8] = {b0.x,b0.y,b0.z,b0.w,b1.x,b1.y,b1.z,b1.w};
            #pragma unroll
            for (int i = 0; i < 8; i++)
                #pragma unroll
                for (int j = 0; j < 8; j++)
                    acc[i][j] += a[i] * b[j];
        }
        __syncthreads();
    }

    float bb[8];
    #pragma unroll
    for (int j = 0; j < 8; j++) bb[j] = bias[n0 + tx + j];

    #pragma unroll
    for (int i = 0; i < 8; i++) {
        float v[8];
        #pragma unroll
        for (int j = 0; j < 8; j++) {
            v[j] = acc[i][j] + bb[j];
            if (doRelu) v[j] = fmaxf(v[j], 0.f);
        }
        float* cp = C + (size_t)(m0 + ty + i) * N + n0 + tx;
        *(float4*)cp       = make_float4(v[0], v[1], v[2], v[3]);
        *(float4*)(cp + 4) = make_float4(v[4], v[5], v[6], v[7]);
    }
}

// ---------------- routing: logits, top-2, softmax, p, expert lists ----------------
__global__ void route_kernel(const float* __restrict__ h2,
                             const float* __restrict__ G3,
                             const float* __restrict__ g3,
                             float* __restrict__ pout)
{
    const int gw   = (blockIdx.x * blockDim.x + threadIdx.x) >> 5;  // token
    const int lane = threadIdx.x & 31;
    if (gw >= NTOK) return;

    const float* hrow = h2 + (size_t)gw * DIN;
    float acc[8] = {0,0,0,0,0,0,0,0};
    for (int k = lane; k < DIN; k += 32) {
        float hv = hrow[k];
        const float4 ga = *(const float4*)(G3 + k * 8);
        const float4 gb = *(const float4*)(G3 + k * 8 + 4);
        acc[0] += hv * ga.x; acc[1] += hv * ga.y;
        acc[2] += hv * ga.z; acc[3] += hv * ga.w;
        acc[4] += hv * gb.x; acc[5] += hv * gb.y;
        acc[6] += hv * gb.z; acc[7] += hv * gb.w;
    }
    #pragma unroll
    for (int e = 0; e < 8; e++)
        #pragma unroll
        for (int o = 16; o; o >>= 1)
            acc[e] += __shfl_xor_sync(0xffffffffu, acc[e], o);

    if (lane == 0) {
        float lg[8];
        #pragma unroll
        for (int e = 0; e < 8; e++) lg[e] = acc[e] + g3[e];

        int i1 = 0; float v1 = lg[0];
        #pragma unroll
        for (int e = 1; e < 8; e++)
            if (lg[e] > v1) { v1 = lg[e]; i1 = e; }
        int i2 = -1; float v2 = -3.4e38f;
        #pragma unroll
        for (int e = 0; e < 8; e++)
            if (e != i1 && lg[e] > v2) { v2 = lg[e]; i2 = e; }

        // softmax over (v1, v2) with v1 >= v2 -> numerically stable
        float ex = expf(v2 - v1);
        float p1 = 1.f / (1.f + ex);
        float p2 = ex  / (1.f + ex);

        float pr[8] = {0,0,0,0,0,0,0,0};
        pr[i1] = p1; pr[i2] = p2;
        float* prow = pout + (size_t)gw * NEXP;
        *(float4*)prow       = make_float4(pr[0], pr[1], pr[2], pr[3]);
        *(float4*)(prow + 4) = make_float4(pr[4], pr[5], pr[6], pr[7]);

        int s1 = atomicAdd(&g_cnt[i1], 1);
        g_list[i1 * NTOK + s1] = gw;
        g_slot[gw * 2 + 0] = i1 * NTOK + s1;
        g_wt  [gw * 2 + 0] = p1;
        int s2 = atomicAdd(&g_cnt[i2], 1);
        g_list[i2 * NTOK + s2] = gw;
        g_slot[gw * 2 + 1] = i2 * NTOK + s2;
        g_wt  [gw * 2 + 1] = p2;
    }
}

// ---------------- FFN1: hid = relu(x[gathered] @ W1[e] + b1[e]) ----------------
__global__ __launch_bounds__(256) void ffn1_kernel(
    const float* __restrict__ x, const float* __restrict__ W1,
    const float* __restrict__ b1)
{
    const int e   = blockIdx.z;
    const int cnt = g_cnt[e];
    const int m0  = blockIdx.y * 128;
    if (m0 >= cnt) return;
    const int n0  = blockIdx.x * 128;

    __shared__ float As[8][128];
    __shared__ float Bs[8][128];
    const int tid = threadIdx.x;
    const int arow = tid >> 1, acol = (tid & 1) * 4;
    const int brow = tid >> 5, bcol = (tid & 31) * 4;
    const int tx = (tid & 15) * 8, ty = (tid >> 4) * 8;

    int r = m0 + arow; if (r >= cnt) r = cnt - 1;
    const int tok = g_list[e * NTOK + r];

    float acc[8][8];
    #pragma unroll
    for (int i = 0; i < 8; i++)
        #pragma unroll
        for (int j = 0; j < 8; j++) acc[i][j] = 0.f;

    const float* Ag = x + (size_t)tok * DIN + acol;
    const float* Bg = W1 + (size_t)e * DIN * HID + (size_t)brow * HID + n0 + bcol;

    for (int k0 = 0; k0 < DIN; k0 += 8) {
        float4 av = *(const float4*)(Ag + k0);
        float4 bv = *(const float4*)(Bg + (size_t)k0 * HID);
        As[acol + 0][arow] = av.x;
        As[acol + 1][arow] = av.y;
        As[acol + 2][arow] = av.z;
        As[acol + 3][arow] = av.w;
        *(float4*)&Bs[brow][bcol] = bv;
        __syncthreads();
        #pragma unroll
        for (int k = 0; k < 8; k++) {
            float4 a0 = *(float4*)&As[k][ty];
            float4 a1 = *(float4*)&As[k][ty + 4];
            float4 b0 = *(float4*)&Bs[k][tx];
            float4 b1 = *(float4*)&Bs[k][tx + 4];
            float a[8] = {a0.x,a0.y,a0.z,a0.w,a1.x,a1.y,a1.z,a1.w};
            float b[8] = {b0.x,b0.y,b0.z,b0.w,b1.x,b1.y,b1.z,b1.w};
            #pragma unroll
            for (int i = 0; i < 8; i++)
                #pragma unroll
                for (int j = 0; j < 8; j++)
                    acc[i][j] += a[i] * b[j];
        }
        __syncthreads();
    }

    float bb[8];
    #pragma unroll
    for (int j = 0; j < 8; j++) bb[j] = b1[e * HID + n0 + tx + j];

    #pragma unroll
    for (int i = 0; i < 8; i++) {
        const int rr = m0 + ty + i;
        if (rr < cnt) {
            float v[8];
            #pragma unroll
            for (int j = 0; j < 8; j++)
                v[j] = fmaxf(acc[i][j] + bb[j], 0.f);
            float* cp = g_hid + ((size_t)e * NTOK + rr) * HID + n0 + tx;
            *(float4*)cp       = make_float4(v[0], v[1], v[2], v[3]);
            *(float4*)(cp + 4) = make_float4(v[4], v[5], v[6], v[7]);
        }
    }
}

// ---------------- FFN2: pout = hid @ W2[e] + b2[e] ----------------
__global__ __launch_bounds__(256) void ffn2_kernel(
    const float* __restrict__ W2, const float* __restrict__ b2)
{
    const int e   = blockIdx.z;
    const int cnt = g_cnt[e];
    const int m0  = blockIdx.y * 128;
    if (m0 >= cnt) return;
    const int n0  = blockIdx.x * 128;

    __shared__ float As[8][128];
    __shared__ float Bs[8][128];
    const int tid = threadIdx.x;
    const int arow = tid >> 1, acol = (tid & 1) * 4;
    const int brow = tid >> 5, bcol = (tid & 31) * 4;
    const int tx = (tid & 15) * 8, ty = (tid >> 4) * 8;

    float acc[8][8];
    #pragma unroll
    for (int i = 0; i < 8; i++)
        #pragma unroll
        for (int j = 0; j < 8; j++) acc[i][j] = 0.f;

    const float* Ag = g_hid + (size_t)e * NTOK * HID + (size_t)(m0 + arow) * HID + acol;
    const float* Bg = W2 + (size_t)e * HID * OUTD + (size_t)brow * OUTD + n0 + bcol;

    for (int k0 = 0; k0 < HID; k0 += 8) {
        float4 av = *(const float4*)(Ag + k0);
        float4 bv = *(const float4*)(Bg + (size_t)k0 * OUTD);
        As[acol + 0][arow] = av.x;
        As[acol + 1][arow] = av.y;
        As[acol + 2][arow] = av.z;
        As[acol + 3][arow] = av.w;
        *(float4*)&Bs[brow][bcol] = bv;
        __syncthreads();
        #pragma unroll
        for (int k = 0; k < 8; k++) {
            float4 a0 = *(float4*)&As[k][ty];
            float4 a1 = *(float4*)&As[k][ty + 4];
            float4 b0 = *(float4*)&Bs[k][tx];
            float4 b1 = *(float4*)&Bs[k][tx + 4];
            float a[8] = {a0.x,a0.y,a0.z,a0.w,a1.x,a1.y,a1.z,a1.w};
            float b[8] = {b0.x,b0.y,b0.z,b0.w,b1.x,b1.y,b1.z,b1.w};
            #pragma unroll
            for (int i = 0; i < 8; i++)
                #pragma unroll
                for (int j = 0; j < 8; j++)
                    acc[i][j] += a[i] * b[j];
        }
        __syncthreads();
    }

    float bb[8];
    #pragma unroll
    for (int j = 0; j < 8; j++) bb[j] = b2[e * OUTD + n0 + tx + j];

    #pragma unroll
    for (int i = 0; i < 8; i++) {
        const int rr = m0 + ty + i;
        if (rr < cnt) {
            float v[8];
            #pragma unroll
            for (int j = 0; j < 8; j++)
                v[j] = acc[i][j] + bb[j];
            float* cp = g_pout + ((size_t)e * NTOK + rr) * OUTD + n0 + tx;
            *(float4*)cp       = make_float4(v[0], v[1], v[2], v[3]);
            *(float4*)(cp + 4) = make_float4(v[4], v[5], v[6], v[7]);
        }
    }
}

// ---------------- combine: y[t] = w0*pout[slot0] + w1*pout[slot1] ----------------
__global__ void combine_kernel(float* __restrict__ y)
{
    const int t = blockIdx.x;
    const int c = threadIdx.x * 4;
    const int s0 = g_slot[t * 2 + 0];
    const int s1 = g_slot[t * 2 + 1];
    const float w0 = g_wt[t * 2 + 0];
    const float w1 = g_wt[t * 2 + 1];
    float4 a = *(const float4*)(g_pout + (size_t)s0 * OUTD + c);
    float4 b = *(const float4*)(g_pout + (size_t)s1 * OUTD + c);
    float4 r;
    r.x = w0 * a.x + w1 * b.x;
    r.y = w0 * a.y + w1 * b.y;
    r.z = w0 * a.z + w1 * b.z;
    r.w = w0 * a.w + w1 * b.w;
    *(float4*)(y + (size_t)t * OUTD + c) = r;
}

// ---------------- launch ----------------
extern "C" void kernel_launch(void* const* d_in, const int* in_sizes, int n_in,
                              void* d_out, int out_size)
{
    const float* x  = (const float*)d_in[0];
    const float* W1 = (const float*)d_in[1];
    const float* b1 = (const float*)d_in[2];
    const float* W2 = (const float*)d_in[3];
    const float* b2 = (const float*)d_in[4];
    const float* G1 = (const float*)d_in[5];
    const float* g1 = (const float*)d_in[6];
    const float* G2 = (const float*)d_in[7];
    const float* g2 = (const float*)d_in[8];
    const float* G3 = (const float*)d_in[9];
    const float* g3 = (const float*)d_in[10];

    float* y = (float*)d_out;
    float* p = (float*)d_out + (size_t)NTOK * OUTD;

    void* tmp;
    cudaGetSymbolAddress(&tmp, g_h1);  float* h1 = (float*)tmp;
    cudaGetSymbolAddress(&tmp, g_h2);  float* h2 = (float*)tmp;

    reset_kernel<<<1, 32>>>();
    // gate layer 1: h1 = relu(x @ G1 + g1)        [8192 x 4096]
    sgemm_gate<<<dim3(GH / 128, NTOK / 128), 256>>>(x, G1, g1, h1, GH, DIN, 1);
    // gate layer 2: h2 = relu(h1 @ G2 + g2)       [8192 x 1024]
    sgemm_gate<<<dim3(DIN / 128, NTOK / 128), 256>>>(h1, G2, g2, h2, DIN, GH, 1);
    // routing: logits, top-2 softmax, p, expert lists
    route_kernel<<<NTOK / 8, 256>>>(h2, G3, g3, p);
    // expert FFN1 (gathered) and FFN2, early-exit on per-expert counts
    ffn1_kernel<<<dim3(HID / 128, NTOK / 128, NEXP), 256>>>(x, W1, b1);
    ffn2_kernel<<<dim3(OUTD / 128, NTOK / 128, NEXP), 256>>>(W2, b2);
    // weighted combine into y
    combine_kernel<<<NTOK, 256>>>(y);
}

// round 3
// speedup vs baseline: 1.4554x; 1.4554x over previous
#include <cuda_runtime.h>
#include <math.h>
#include <stdint.h>

#define NTOK 8192
#define DIN  1024
#define NEXP 8
#define HID  4096
#define OUTD 1024
#define GH   4096

// ---------------- scratch ----------------
__device__ float g_h1 [(size_t)NTOK * GH];
__device__ float g_h2 [(size_t)NTOK * DIN];
__device__ float g_hid [(size_t)NEXP * NTOK * HID];
__device__ float g_pout[(size_t)NEXP * NTOK * OUTD];
__device__ int   g_cnt [NEXP];
__device__ int   g_list[NEXP * NTOK];
__device__ int   g_slot[NTOK * 2];
__device__ float g_wt  [NTOK * 2];

__device__ __forceinline__ float tf32r(float x) {
    float r; asm("cvt.rna.tf32.f32 %0, %1;" : "=f"(r) : "f"(x)); return r;
}

__device__ __forceinline__ void mma_tf32(float* c, const uint32_t* a, const uint32_t* b) {
    asm volatile(
        "mma.sync.aligned.m16n8k8.row.col.f32.tf32.tf32.f32 "
        "{%0,%1,%2,%3}, {%4,%5,%6,%7}, {%8,%9}, {%0,%1,%2,%3};\n"
        : "+f"(c[0]), "+f"(c[1]), "+f"(c[2]), "+f"(c[3])
        : "r"(a[0]), "r"(a[1]), "r"(a[2]), "r"(a[3]), "r"(b[0]), "r"(b[1]));
}

// smem plane: [16][136] floats; planes: 0=Ahi 1=Alo 2=Bhi 3=Blo, x2 stages
#define PLANE (16 * 136)
#define POFF(s, w) (((s) * 4 + (w)) * PLANE)
#define SMEM_BYTES (8 * PLANE * 4)   // 69632

// ---------------- reset ----------------
__global__ void reset_kernel() {
    if (threadIdx.x < NEXP) g_cnt[threadIdx.x] = 0;
}

// ---------------- 3xTF32 GEMM: C = (A @ B + bias)[relu], B row-major [K,N] ----------------
__global__ __launch_bounds__(256, 1) void gemm_tc(
    const float* __restrict__ A, size_t sAe,
    const float* __restrict__ B, size_t sBe,
    const float* __restrict__ bias, size_t sBiasE,
    float* __restrict__ C, size_t sCe,
    int K, int N, int doRelu,
    const int* __restrict__ list, const int* __restrict__ cntArr)
{
    const int e   = blockIdx.z;
    const int cnt = cntArr ? cntArr[e] : (int)(gridDim.y * 128);
    const int m0  = blockIdx.y * 128;
    if (m0 >= cnt) return;
    const int n0  = blockIdx.x * 128;

    extern __shared__ float smem[];

    const int tid  = threadIdx.x;
    const int wid  = tid >> 5;
    const int lane = tid & 31;
    const int wm0  = (wid >> 1) * 32;   // warp m offset in tile
    const int wn0  = (wid & 1) * 64;    // warp n offset in tile

    // ---- loader indices ----
    // A: row ar = tid>>1 (tile row), cols [ac, ac+8)
    const int ar = tid >> 1;
    const int ac = (tid & 1) * 8;
    int arow = m0 + ar; if (arow > cnt - 1) arow = cnt - 1;
    if (list) arow = list[e * NTOK + arow];
    const float* Ap = A + sAe * e + (size_t)arow * K + ac;
    // B: k-row bk = tid>>4, cols [bn, bn+8)
    const int bk = tid >> 4;
    const int bn = (tid & 15) * 8;
    const float* Bp = B + sBe * e + (size_t)bk * N + n0 + bn;

    float4 pa0, pa1, pb0, pb1;
    const int T = K >> 4;

    auto load_regs = [&](int kt) {
        const float* ap = Ap + kt * 16;
        pa0 = *(const float4*)(ap);
        pa1 = *(const float4*)(ap + 4);
        const float* bp = Bp + (size_t)(kt * 16) * N;
        pb0 = *(const float4*)(bp);
        pb1 = *(const float4*)(bp + 4);
    };
    auto store_smem = [&](int s) {
        float av[8] = {pa0.x, pa0.y, pa0.z, pa0.w, pa1.x, pa1.y, pa1.z, pa1.w};
        float* ah = smem + POFF(s, 0);
        float* al = smem + POFF(s, 1);
        #pragma unroll
        for (int j = 0; j < 8; j++) {
            float h = tf32r(av[j]);
            ah[(ac + j) * 136 + ar] = h;
            al[(ac + j) * 136 + ar] = av[j] - h;
        }
        float bv[8] = {pb0.x, pb0.y, pb0.z, pb0.w, pb1.x, pb1.y, pb1.z, pb1.w};
        float* bh = smem + POFF(s, 2);
        float* bl = smem + POFF(s, 3);
        #pragma unroll
        for (int j = 0; j < 8; j++) {
            float h = tf32r(bv[j]);
            bh[bk * 136 + bn + j] = h;
            bl[bk * 136 + bn + j] = bv[j] - h;
        }
    };

    float acc[2][8][4];
    #pragma unroll
    for (int im = 0; im < 2; im++)
        #pragma unroll
        for (int jn = 0; jn < 8; jn++)
            #pragma unroll
            for (int q = 0; q < 4; q++) acc[im][jn][q] = 0.f;

    load_regs(0);
    store_smem(0);
    __syncthreads();

    const int fm = wm0 + (lane >> 2);   // fragment base row in tile
    const int fk = lane & 3;            // fragment k offset
    const int fn = wn0 + (lane >> 2);   // fragment base col in tile

    for (int kt = 0; kt < T; ++kt) {
        const int s = kt & 1;
        if (kt + 1 < T) load_regs(kt + 1);

        const uint32_t* ash = (const uint32_t*)(smem + POFF(s, 0));
        const uint32_t* asl = (const uint32_t*)(smem + POFF(s, 1));
        const uint32_t* bsh = (const uint32_t*)(smem + POFF(s, 2));
        const uint32_t* bsl = (const uint32_t*)(smem + POFF(s, 3));

        #pragma unroll
        for (int ks = 0; ks < 16; ks += 8) {
            uint32_t ah[2][4], al[2][4], bh[8][2], bl[8][2];
            #pragma unroll
            for (int im = 0; im < 2; im++) {
                const int m = fm + im * 16;
                const int k = ks + fk;
                ah[im][0] = ash[(k)     * 136 + m];
                ah[im][1] = ash[(k)     * 136 + m + 8];
                ah[im][2] = ash[(k + 4) * 136 + m];
                ah[im][3] = ash[(k + 4) * 136 + m + 8];
                al[im][0] = asl[(k)     * 136 + m];
                al[im][1] = asl[(k)     * 136 + m + 8];
                al[im][2] = asl[(k + 4) * 136 + m];
                al[im][3] = asl[(k + 4) * 136 + m + 8];
            }
            #pragma unroll
            for (int jn = 0; jn < 8; jn++) {
                const int n = fn + jn * 8;
                const int k = ks + fk;
                bh[jn][0] = bsh[(k)     * 136 + n];
                bh[jn][1] = bsh[(k + 4) * 136 + n];
                bl[jn][0] = bsl[(k)     * 136 + n];
                bl[jn][1] = bsl[(k + 4) * 136 + n];
            }
            #pragma unroll
            for (int im = 0; im < 2; im++)
                #pragma unroll
                for (int jn = 0; jn < 8; jn++) {
                    mma_tf32(acc[im][jn], ah[im], bh[jn]);
                    mma_tf32(acc[im][jn], ah[im], bl[jn]);
                    mma_tf32(acc[im][jn], al[im], bh[jn]);
                }
        }

        if (kt + 1 < T) store_smem(s ^ 1);
        __syncthreads();
    }

    // ---- epilogue: bias + relu + store ----
    const float* bp = bias + sBiasE * e + n0;
    float* Cbase = C + sCe * e;
    #pragma unroll
    for (int im = 0; im < 2; im++) {
        #pragma unroll
        for (int half = 0; half < 2; half++) {
            const int rr = m0 + wm0 + im * 16 + (lane >> 2) + half * 8;
            if (rr < cnt) {
                float* crow = Cbase + (size_t)rr * N + n0;
                #pragma unroll
                for (int jn = 0; jn < 8; jn++) {
                    const int col = wn0 + jn * 8 + (lane & 3) * 2;
                    float v0 = acc[im][jn][half * 2 + 0] + bp[col];
                    float v1 = acc[im][jn][half * 2 + 1] + bp[col + 1];
                    if (doRelu) { v0 = fmaxf(v0, 0.f); v1 = fmaxf(v1, 0.f); }
                    *(float2*)(crow + col) = make_float2(v0, v1);
                }
            }
        }
    }
}

// ---------------- routing ----------------
__global__ void route_kernel(const float* __restrict__ h2,
                             const float* __restrict__ G3,
                             const float* __restrict__ g3,
                             float* __restrict__ pout)
{
    const int gw   = (blockIdx.x * blockDim.x + threadIdx.x) >> 5;
    const int lane = threadIdx.x & 31;
    if (gw >= NTOK) return;

    const float* hrow = h2 + (size_t)gw * DIN;
    float acc[8] = {0,0,0,0,0,0,0,0};
    for (int k = lane; k < DIN; k += 32) {
        float hv = hrow[k];
        const float4 ga = *(const float4*)(G3 + k * 8);
        const float4 gb = *(const float4*)(G3 + k * 8 + 4);
        acc[0] += hv * ga.x; acc[1] += hv * ga.y;
        acc[2] += hv * ga.z; acc[3] += hv * ga.w;
        acc[4] += hv * gb.x; acc[5] += hv * gb.y;
        acc[6] += hv * gb.z; acc[7] += hv * gb.w;
    }
    #pragma unroll
    for (int e = 0; e < 8; e++)
        #pragma unroll
        for (int o = 16; o; o >>= 1)
            acc[e] += __shfl_xor_sync(0xffffffffu, acc[e], o);

    if (lane == 0) {
        float lg[8];
        #pragma unroll
        for (int e = 0; e < 8; e++) lg[e] = acc[e] + g3[e];

        int i1 = 0; float v1 = lg[0];
        #pragma unroll
        for (int e = 1; e < 8; e++)
            if (lg[e] > v1) { v1 = lg[e]; i1 = e; }
        int i2 = -1; float v2 = -3.4e38f;
        #pragma unroll
        for (int e = 0; e < 8; e++)
            if (e != i1 && lg[e] > v2) { v2 = lg[e]; i2 = e; }

        float ex = expf(v2 - v1);
        float p1 = 1.f / (1.f + ex);
        float p2 = ex  / (1.f + ex);

        float pr[8] = {0,0,0,0,0,0,0,0};
        pr[i1] = p1; pr[i2] = p2;
        float* prow = pout + (size_t)gw * NEXP;
        *(float4*)prow       = make_float4(pr[0], pr[1], pr[2], pr[3]);
        *(float4*)(prow + 4) = make_float4(pr[4], pr[5], pr[6], pr[7]);

        int s1 = atomicAdd(&g_cnt[i1], 1);
        g_list[i1 * NTOK + s1] = gw;
        g_slot[gw * 2 + 0] = i1 * NTOK + s1;
        g_wt  [gw * 2 + 0] = p1;
        int s2 = atomicAdd(&g_cnt[i2], 1);
        g_list[i2 * NTOK + s2] = gw;
        g_slot[gw * 2 + 1] = i2 * NTOK + s2;
        g_wt  [gw * 2 + 1] = p2;
    }
}

// ---------------- combine ----------------
__global__ void combine_kernel(float* __restrict__ y)
{
    const int t = blockIdx.x;
    const int c = threadIdx.x * 4;
    const int s0 = g_slot[t * 2 + 0];
    const int s1 = g_slot[t * 2 + 1];
    const float w0 = g_wt[t * 2 + 0];
    const float w1 = g_wt[t * 2 + 1];
    float4 a = *(const float4*)(g_pout + (size_t)s0 * OUTD + c);
    float4 b = *(const float4*)(g_pout + (size_t)s1 * OUTD + c);
    float4 rr;
    rr.x = w0 * a.x + w1 * b.x;
    rr.y = w0 * a.y + w1 * b.y;
    rr.z = w0 * a.z + w1 * b.z;
    rr.w = w0 * a.w + w1 * b.w;
    *(float4*)(y + (size_t)t * OUTD + c) = rr;
}

// ---------------- launch ----------------
extern "C" void kernel_launch(void* const* d_in, const int* in_sizes, int n_in,
                              void* d_out, int out_size)
{
    const float* x  = (const float*)d_in[0];
    const float* W1 = (const float*)d_in[1];
    const float* b1 = (const float*)d_in[2];
    const float* W2 = (const float*)d_in[3];
    const float* b2 = (const float*)d_in[4];
    const float* G1 = (const float*)d_in[5];
    const float* g1 = (const float*)d_in[6];
    const float* G2 = (const float*)d_in[7];
    const float* g2 = (const float*)d_in[8];
    const float* G3 = (const float*)d_in[9];
    const float* g3 = (const float*)d_in[10];

    float* y = (float*)d_out;
    float* p = (float*)d_out + (size_t)NTOK * OUTD;

    void* tmp;
    cudaGetSymbolAddress(&tmp, g_h1);   float* h1  = (float*)tmp;
    cudaGetSymbolAddress(&tmp, g_h2);   float* h2  = (float*)tmp;
    cudaGetSymbolAddress(&tmp, g_hid);  float* hid = (float*)tmp;
    cudaGetSymbolAddress(&tmp, g_pout); float* po  = (float*)tmp;
    cudaGetSymbolAddress(&tmp, g_list); int*   lst = (int*)tmp;
    cudaGetSymbolAddress(&tmp, g_cnt);  int*   cnt = (int*)tmp;

    cudaFuncSetAttribute(gemm_tc, cudaFuncAttributeMaxDynamicSharedMemorySize, SMEM_BYTES);

    reset_kernel<<<1, 32>>>();

    // gate layer 1: h1 = relu(x @ G1 + g1)        [8192 x 4096]
    gemm_tc<<<dim3(GH / 128, NTOK / 128, 1), 256, SMEM_BYTES>>>(
        x, 0, G1, 0, g1, 0, h1, 0, DIN, GH, 1, nullptr, nullptr);
    // gate layer 2: h2 = relu(h1 @ G2 + g2)       [8192 x 1024]
    gemm_tc<<<dim3(DIN / 128, NTOK / 128, 1), 256, SMEM_BYTES>>>(
        h1, 0, G2, 0, g2, 0, h2, 0, GH, DIN, 1, nullptr, nullptr);
    // routing
    route_kernel<<<NTOK / 8, 256>>>(h2, G3, g3, p);
    // expert FFN1: hid = relu(x[list] @ W1[e] + b1[e])
    gemm_tc<<<dim3(HID / 128, NTOK / 128, NEXP), 256, SMEM_BYTES>>>(
        x, 0, W1, (size_t)DIN * HID, b1, HID, hid, (size_t)NTOK * HID,
        DIN, HID, 1, lst, cnt);
    // expert FFN2: pout = hid @ W2[e] + b2[e]
    gemm_tc<<<dim3(OUTD / 128, NTOK / 128, NEXP), 256, SMEM_BYTES>>>(
        hid, (size_t)NTOK * HID, W2, (size_t)HID * OUTD, b2, OUTD, po, (size_t)NTOK * OUTD,
        HID, OUTD, 0, nullptr, cnt);
    // combine
    combine_kernel<<<NTOK, 256>>>(y);
}

// round 4
// speedup vs baseline: 1.6119x; 1.1075x over previous
#include <cuda_runtime.h>
#include <math.h>
#include <stdint.h>

#define NTOK 8192
#define DIN  1024
#define NEXP 8
#define HID  4096
#define OUTD 1024
#define GH   4096

// ---------------- scratch ----------------
__device__ float g_h1 [(size_t)NTOK * GH];
__device__ float g_h2 [(size_t)NTOK * DIN];
__device__ float g_hid [(size_t)NEXP * NTOK * HID];
__device__ float g_pout[(size_t)NEXP * NTOK * OUTD];
__device__ int   g_cnt [NEXP];
__device__ int   g_list[NEXP * NTOK];
__device__ int   g_slot[NTOK * 2];
__device__ float g_wt  [NTOK * 2];

__device__ __forceinline__ float tf32r(float x) {
    float r; asm("cvt.rna.tf32.f32 %0, %1;" : "=f"(r) : "f"(x)); return r;
}

__device__ __forceinline__ void mma_tf32(float* c, const uint32_t* a, const uint32_t* b) {
    asm volatile(
        "mma.sync.aligned.m16n8k8.row.col.f32.tf32.tf32.f32 "
        "{%0,%1,%2,%3}, {%4,%5,%6,%7}, {%8,%9}, {%0,%1,%2,%3};\n"
        : "+f"(c[0]), "+f"(c[1]), "+f"(c[2]), "+f"(c[3])
        : "r"(a[0]), "r"(a[1]), "r"(a[2]), "r"(a[3]), "r"(b[0]), "r"(b[1]));
}

// smem plane: [16][136] floats. Plane order per stage: 0=Ahi 1=Bhi 2=Blo [3=Alo iff NTERMS==3]
#define PLANE (16 * 136)
#define SMEM_BYTES_3 (8 * PLANE * 4)   // 69632
#define SMEM_BYTES_2 (6 * PLANE * 4)   // 52224

// ---------------- reset ----------------
__global__ void reset_kernel() {
    if (threadIdx.x < NEXP) g_cnt[threadIdx.x] = 0;
}

// ---------------- NTERMS x TF32 GEMM: C = (A @ B + bias)[relu], B row-major [K,N] ----------------
template<int NTERMS>
__global__ __launch_bounds__(256, 1) void gemm_tc(
    const float* __restrict__ A, size_t sAe,
    const float* __restrict__ B, size_t sBe,
    const float* __restrict__ bias, size_t sBiasE,
    float* __restrict__ C, size_t sCe,
    int K, int N, int doRelu,
    const int* __restrict__ list, const int* __restrict__ cntArr)
{
    const int NP = (NTERMS == 3) ? 4 : 3;   // planes per stage
    const int e   = blockIdx.z;
    const int cnt = cntArr ? cntArr[e] : (int)(gridDim.y * 128);
    const int m0  = blockIdx.y * 128;
    if (m0 >= cnt) return;
    const int n0  = blockIdx.x * 128;

    extern __shared__ float smem[];

    const int tid  = threadIdx.x;
    const int wid  = tid >> 5;
    const int lane = tid & 31;
    const int wm0  = (wid >> 1) * 32;
    const int wn0  = (wid & 1) * 64;

    const int ar = tid >> 1;
    const int ac = (tid & 1) * 8;
    int arow = m0 + ar; if (arow > cnt - 1) arow = cnt - 1;
    if (list) arow = list[e * NTOK + arow];
    const float* Ap = A + sAe * e + (size_t)arow * K + ac;
    const int bk = tid >> 4;
    const int bn = (tid & 15) * 8;
    const float* Bp = B + sBe * e + (size_t)bk * N + n0 + bn;

    float4 pa0, pa1, pb0, pb1;
    const int T = K >> 4;

    auto load_regs = [&](int kt) {
        const float* ap = Ap + kt * 16;
        pa0 = *(const float4*)(ap);
        pa1 = *(const float4*)(ap + 4);
        const float* bp = Bp + (size_t)(kt * 16) * N;
        pb0 = *(const float4*)(bp);
        pb1 = *(const float4*)(bp + 4);
    };
    auto store_smem = [&](int s) {
        float av[8] = {pa0.x, pa0.y, pa0.z, pa0.w, pa1.x, pa1.y, pa1.z, pa1.w};
        float* ah = smem + (s * NP + 0) * PLANE;
        float* al = smem + (s * NP + 3) * PLANE;
        #pragma unroll
        for (int j = 0; j < 8; j++) {
            float h = tf32r(av[j]);
            ah[(ac + j) * 136 + ar] = h;
            if (NTERMS == 3) al[(ac + j) * 136 + ar] = av[j] - h;
        }
        float bv[8] = {pb0.x, pb0.y, pb0.z, pb0.w, pb1.x, pb1.y, pb1.z, pb1.w};
        float* bh = smem + (s * NP + 1) * PLANE;
        float* bl = smem + (s * NP + 2) * PLANE;
        #pragma unroll
        for (int j = 0; j < 8; j++) {
            float h = tf32r(bv[j]);
            bh[bk * 136 + bn + j] = h;
            bl[bk * 136 + bn + j] = bv[j] - h;
        }
    };

    float acc[2][8][4];
    #pragma unroll
    for (int im = 0; im < 2; im++)
        #pragma unroll
        for (int jn = 0; jn < 8; jn++)
            #pragma unroll
            for (int q = 0; q < 4; q++) acc[im][jn][q] = 0.f;

    load_regs(0);
    store_smem(0);
    __syncthreads();

    const int fm = wm0 + (lane >> 2);
    const int fk = lane & 3;
    const int fn = wn0 + (lane >> 2);

    for (int kt = 0; kt < T; ++kt) {
        const int s = kt & 1;
        if (kt + 1 < T) load_regs(kt + 1);

        const uint32_t* ash = (const uint32_t*)(smem + (s * NP + 0) * PLANE);
        const uint32_t* bsh = (const uint32_t*)(smem + (s * NP + 1) * PLANE);
        const uint32_t* bsl = (const uint32_t*)(smem + (s * NP + 2) * PLANE);
        const uint32_t* asl = (const uint32_t*)(smem + (s * NP + 3) * PLANE);

        #pragma unroll
        for (int ks = 0; ks < 16; ks += 8) {
            uint32_t ah[2][4], al[2][4], bh[8][2], bl[8][2];
            #pragma unroll
            for (int im = 0; im < 2; im++) {
                const int m = fm + im * 16;
                const int k = ks + fk;
                ah[im][0] = ash[(k)     * 136 + m];
                ah[im][1] = ash[(k)     * 136 + m + 8];
                ah[im][2] = ash[(k + 4) * 136 + m];
                ah[im][3] = ash[(k + 4) * 136 + m + 8];
                if (NTERMS == 3) {
                    al[im][0] = asl[(k)     * 136 + m];
                    al[im][1] = asl[(k)     * 136 + m + 8];
                    al[im][2] = asl[(k + 4) * 136 + m];
                    al[im][3] = asl[(k + 4) * 136 + m + 8];
                }
            }
            #pragma unroll
            for (int jn = 0; jn < 8; jn++) {
                const int n = fn + jn * 8;
                const int k = ks + fk;
                bh[jn][0] = bsh[(k)     * 136 + n];
                bh[jn][1] = bsh[(k + 4) * 136 + n];
                bl[jn][0] = bsl[(k)     * 136 + n];
                bl[jn][1] = bsl[(k + 4) * 136 + n];
            }
            #pragma unroll
            for (int im = 0; im < 2; im++)
                #pragma unroll
                for (int jn = 0; jn < 8; jn++) {
                    mma_tf32(acc[im][jn], ah[im], bh[jn]);
                    mma_tf32(acc[im][jn], ah[im], bl[jn]);
                    if (NTERMS == 3) mma_tf32(acc[im][jn], al[im], bh[jn]);
                }
        }

        if (kt + 1 < T) store_smem(s ^ 1);
        __syncthreads();
    }

    // ---- epilogue: bias + relu + store ----
    const float* bp = bias + sBiasE * e + n0;
    float* Cbase = C + sCe * e;
    #pragma unroll
    for (int im = 0; im < 2; im++) {
        #pragma unroll
        for (int half = 0; half < 2; half++) {
            const int rr = m0 + wm0 + im * 16 + (lane >> 2) + half * 8;
            if (rr < cnt) {
                float* crow = Cbase + (size_t)rr * N + n0;
                #pragma unroll
                for (int jn = 0; jn < 8; jn++) {
                    const int col = wn0 + jn * 8 + (lane & 3) * 2;
                    float v0 = acc[im][jn][half * 2 + 0] + bp[col];
                    float v1 = acc[im][jn][half * 2 + 1] + bp[col + 1];
                    if (doRelu) { v0 = fmaxf(v0, 0.f); v1 = fmaxf(v1, 0.f); }
                    *(float2*)(crow + col) = make_float2(v0, v1);
                }
            }
        }
    }
}

// ---------------- routing ----------------
__global__ void route_kernel(const float* __restrict__ h2,
                             const float* __restrict__ G3,
                             const float* __restrict__ g3,
                             float* __restrict__ pout)
{
    const int gw   = (blockIdx.x * blockDim.x + threadIdx.x) >> 5;
    const int lane = threadIdx.x & 31;
    if (gw >= NTOK) return;

    const float* hrow = h2 + (size_t)gw * DIN;
    float acc[8] = {0,0,0,0,0,0,0,0};
    for (int k = lane; k < DIN; k += 32) {
        float hv = hrow[k];
        const float4 ga = *(const float4*)(G3 + k * 8);
        const float4 gb = *(const float4*)(G3 + k * 8 + 4);
        acc[0] += hv * ga.x; acc[1] += hv * ga.y;
        acc[2] += hv * ga.z; acc[3] += hv * ga.w;
        acc[4] += hv * gb.x; acc[5] += hv * gb.y;
        acc[6] += hv * gb.z; acc[7] += hv * gb.w;
    }
    #pragma unroll
    for (int e = 0; e < 8; e++)
        #pragma unroll
        for (int o = 16; o; o >>= 1)
            acc[e] += __shfl_xor_sync(0xffffffffu, acc[e], o);

    if (lane == 0) {
        float lg[8];
        #pragma unroll
        for (int e = 0; e < 8; e++) lg[e] = acc[e] + g3[e];

        int i1 = 0; float v1 = lg[0];
        #pragma unroll
        for (int e = 1; e < 8; e++)
            if (lg[e] > v1) { v1 = lg[e]; i1 = e; }
        int i2 = -1; float v2 = -3.4e38f;
        #pragma unroll
        for (int e = 0; e < 8; e++)
            if (e != i1 && lg[e] > v2) { v2 = lg[e]; i2 = e; }

        float ex = expf(v2 - v1);
        float p1 = 1.f / (1.f + ex);
        float p2 = ex  / (1.f + ex);

        float pr[8] = {0,0,0,0,0,0,0,0};
        pr[i1] = p1; pr[i2] = p2;
        float* prow = pout + (size_t)gw * NEXP;
        *(float4*)prow       = make_float4(pr[0], pr[1], pr[2], pr[3]);
        *(float4*)(prow + 4) = make_float4(pr[4], pr[5], pr[6], pr[7]);

        int s1 = atomicAdd(&g_cnt[i1], 1);
        g_list[i1 * NTOK + s1] = gw;
        g_slot[gw * 2 + 0] = i1 * NTOK + s1;
        g_wt  [gw * 2 + 0] = p1;
        int s2 = atomicAdd(&g_cnt[i2], 1);
        g_list[i2 * NTOK + s2] = gw;
        g_slot[gw * 2 + 1] = i2 * NTOK + s2;
        g_wt  [gw * 2 + 1] = p2;
    }
}

// ---------------- combine ----------------
__global__ void combine_kernel(float* __restrict__ y)
{
    const int t = blockIdx.x;
    const int c = threadIdx.x * 4;
    const int s0 = g_slot[t * 2 + 0];
    const int s1 = g_slot[t * 2 + 1];
    const float w0 = g_wt[t * 2 + 0];
    const float w1 = g_wt[t * 2 + 1];
    float4 a = *(const float4*)(g_pout + (size_t)s0 * OUTD + c);
    float4 b = *(const float4*)(g_pout + (size_t)s1 * OUTD + c);
    float4 rr;
    rr.x = w0 * a.x + w1 * b.x;
    rr.y = w0 * a.y + w1 * b.y;
    rr.z = w0 * a.z + w1 * b.z;
    rr.w = w0 * a.w + w1 * b.w;
    *(float4*)(y + (size_t)t * OUTD + c) = rr;
}

// ---------------- launch ----------------
extern "C" void kernel_launch(void* const* d_in, const int* in_sizes, int n_in,
                              void* d_out, int out_size)
{
    const float* x  = (const float*)d_in[0];
    const float* W1 = (const float*)d_in[1];
    const float* b1 = (const float*)d_in[2];
    const float* W2 = (const float*)d_in[3];
    const float* b2 = (const float*)d_in[4];
    const float* G1 = (const float*)d_in[5];
    const float* g1 = (const float*)d_in[6];
    const float* G2 = (const float*)d_in[7];
    const float* g2 = (const float*)d_in[8];
    const float* G3 = (const float*)d_in[9];
    const float* g3 = (const float*)d_in[10];

    float* y = (float*)d_out;
    float* p = (float*)d_out + (size_t)NTOK * OUTD;

    void* tmp;
    cudaGetSymbolAddress(&tmp, g_h1);   float* h1  = (float*)tmp;
    cudaGetSymbolAddress(&tmp, g_h2);   float* h2  = (float*)tmp;
    cudaGetSymbolAddress(&tmp, g_hid);  float* hid = (float*)tmp;
    cudaGetSymbolAddress(&tmp, g_pout); float* po  = (float*)tmp;
    cudaGetSymbolAddress(&tmp, g_list); int*   lst = (int*)tmp;
    cudaGetSymbolAddress(&tmp, g_cnt);  int*   cnt = (int*)tmp;

    cudaFuncSetAttribute(gemm_tc<3>, cudaFuncAttributeMaxDynamicSharedMemorySize, SMEM_BYTES_3);
    cudaFuncSetAttribute(gemm_tc<2>, cudaFuncAttributeMaxDynamicSharedMemorySize, SMEM_BYTES_2);

    reset_kernel<<<1, 32>>>();

    // gate layer 1: h1 = relu(x @ G1 + g1)   — 3-term (selection-critical path)
    gemm_tc<3><<<dim3(GH / 128, NTOK / 128, 1), 256, SMEM_BYTES_3>>>(
        x, 0, G1, 0, g1, 0, h1, 0, DIN, GH, 1, nullptr, nullptr);
    // gate layer 2: h2 = relu(h1 @ G2 + g2)  — 3-term
    gemm_tc<3><<<dim3(DIN / 128, NTOK / 128, 1), 256, SMEM_BYTES_3>>>(
        h1, 0, G2, 0, g2, 0, h2, 0, GH, DIN, 1, nullptr, nullptr);
    // routing
    route_kernel<<<NTOK / 8, 256>>>(h2, G3, g3, p);
    // expert FFN1: hid = relu(x[list] @ W1[e] + b1[e])  — 2-term (value path)
    gemm_tc<2><<<dim3(HID / 128, NTOK / 128, NEXP), 256, SMEM_BYTES_2>>>(
        x, 0, W1, (size_t)DIN * HID, b1, HID, hid, (size_t)NTOK * HID,
        DIN, HID, 1, lst, cnt);
    // expert FFN2: pout = hid @ W2[e] + b2[e]  — 2-term
    gemm_tc<2><<<dim3(OUTD / 128, NTOK / 128, NEXP), 256, SMEM_BYTES_2>>>(
        hid, (size_t)NTOK * HID, W2, (size_t)HID * OUTD, b2, OUTD, po, (size_t)NTOK * OUTD,
        HID, OUTD, 0, nullptr, cnt);
    // combine
    combine_kernel<<<NTOK, 256>>>(y);
}

// round 5
// speedup vs baseline: 1.6427x; 1.0191x over previous
#include <cuda_runtime.h>
#include <math.h>
#include <stdint.h>

#define NTOK 8192
#define DIN  1024
#define NEXP 8
#define HID  4096
#define OUTD 1024
#define GH   4096

// ---------------- scratch ----------------
__device__ float g_h1 [(size_t)NTOK * GH];
__device__ float g_h2 [(size_t)NTOK * DIN];
__device__ float g_hid [(size_t)NEXP * NTOK * HID];
__device__ float g_pout[(size_t)NEXP * NTOK * OUTD];
__device__ int   g_cnt [NEXP];
__device__ int   g_list[NEXP * NTOK];
__device__ int   g_slot[NTOK * 2];
__device__ float g_wt  [NTOK * 2];

__device__ __forceinline__ float tf32r(float x) {
    float r; asm("cvt.rna.tf32.f32 %0, %1;" : "=f"(r) : "f"(x)); return r;
}
__device__ __forceinline__ uint32_t cvta_s(const void* p) {
    uint32_t a;
    asm("{ .reg .u64 t; cvta.to.shared.u64 t, %1; cvt.u32.u64 %0, t; }" : "=r"(a) : "l"(p));
    return a;
}
#define CP16(d, s)  asm volatile("cp.async.ca.shared.global [%0], [%1], 16;" :: "r"(d), "l"(s))
#define CPCOMMIT()  asm volatile("cp.async.commit_group;" ::: "memory")
#define CPWAIT1()   asm volatile("cp.async.wait_group 1;" ::: "memory")

__device__ __forceinline__ void mma_tf32(float* c, const uint32_t* a, const uint32_t* b) {
    asm volatile(
        "mma.sync.aligned.m16n8k8.row.col.f32.tf32.tf32.f32 "
        "{%0,%1,%2,%3}, {%4,%5,%6,%7}, {%8,%9}, {%0,%1,%2,%3};\n"
        : "+f"(c[0]), "+f"(c[1]), "+f"(c[2]), "+f"(c[3])
        : "r"(a[0]), "r"(a[1]), "r"(a[2]), "r"(a[3]), "r"(b[0]), "r"(b[1]));
}

// SMEM: per stage: A raw [128 rows][20 floats] (stride 20 -> conflict-free frags),
//                  B raw [16 k][136 n]
#define A_STRIDE 20
#define A_PLANE  (128 * A_STRIDE)          // 2560 floats
#define B_PLANE  (16 * 136)                // 2176 floats
#define STAGE_F  (A_PLANE + B_PLANE)       // 4736 floats
#define NSTAGE   3
#define SMEM_BYTES (NSTAGE * STAGE_F * 4)  // 56832

// ---------------- reset ----------------
__global__ void reset_kernel() {
    if (threadIdx.x < NEXP) g_cnt[threadIdx.x] = 0;
}

// ---------------- NTERMS x TF32 GEMM: C = (A @ B + bias)[relu], B row-major [K,N] ----------------
// 128 threads, 4 warps, warp tile 64x64, CTA tile 128x128, BK=16, cp.async 3-stage ring.
template<int NTERMS>
__global__ __launch_bounds__(128) void gemm_tc(
    const float* __restrict__ A, size_t sAe,
    const float* __restrict__ B, size_t sBe,
    const float* __restrict__ bias, size_t sBiasE,
    float* __restrict__ C, size_t sCe,
    int K, int N, int doRelu,
    const int* __restrict__ list, const int* __restrict__ cntArr)
{
    const int e   = blockIdx.z;
    const int cnt = cntArr ? cntArr[e] : (int)(gridDim.y * 128);
    const int m0  = blockIdx.y * 128;
    if (m0 >= cnt) return;
    const int n0  = blockIdx.x * 128;

    extern __shared__ float smem[];
    const uint32_t sbase = cvta_s(smem);

    const int tid  = threadIdx.x;
    const int wid  = tid >> 5;
    const int lane = tid & 31;
    const int wm0  = (wid >> 1) * 64;
    const int wn0  = (wid & 1) * 64;

    // loaders: A row = tid, 16 k per chunk; B: bk = tid>>3 (16 rows), bn = (tid&7)*16
    int arow = m0 + tid; if (arow > cnt - 1) arow = cnt - 1;
    if (list) arow = list[e * NTOK + arow];
    const float* Ap = A + sAe * e + (size_t)arow * K;
    const int bk = tid >> 3;
    const int bn = (tid & 7) * 16;
    const float* Bp = B + sBe * e + (size_t)bk * N + n0 + bn;
    const uint32_t adst0 = sbase + (uint32_t)(tid * A_STRIDE) * 4u;
    const uint32_t bdst0 = sbase + (uint32_t)(A_PLANE + bk * 136 + bn) * 4u;

    const int T = K >> 4;

    auto issue = [&](int kt, int s) {
        const float* ap = Ap + kt * 16;
        uint32_t ad = adst0 + (uint32_t)(s * STAGE_F) * 4u;
        CP16(ad,      ap);
        CP16(ad + 16, ap + 4);
        CP16(ad + 32, ap + 8);
        CP16(ad + 48, ap + 12);
        const float* bp = Bp + (size_t)kt * 16 * N;
        uint32_t bd = bdst0 + (uint32_t)(s * STAGE_F) * 4u;
        CP16(bd,      bp);
        CP16(bd + 16, bp + 4);
        CP16(bd + 32, bp + 8);
        CP16(bd + 48, bp + 12);
    };

    float acc[4][8][4];
    #pragma unroll
    for (int im = 0; im < 4; im++)
        #pragma unroll
        for (int jn = 0; jn < 8; jn++)
            #pragma unroll
            for (int q = 0; q < 4; q++) acc[im][jn][q] = 0.f;

    issue(0, 0); CPCOMMIT();
    if (T > 1) issue(1, 1);
    CPCOMMIT();

    const int fr = lane >> 2;       // fragment row/col within-frag offset
    const int fk = lane & 3;

    for (int kt = 0; kt < T; ++kt) {
        CPWAIT1();
        __syncthreads();
        const int s = kt % NSTAGE;
        const float* As_ = smem + s * STAGE_F;
        const float* Bs_ = smem + s * STAGE_F + A_PLANE;

        #pragma unroll
        for (int ks = 0; ks < 16; ks += 8) {
            const int k = ks + fk;
            // raw fragment loads
            float arw[4][4];
            #pragma unroll
            for (int im = 0; im < 4; im++) {
                const int m = wm0 + im * 16 + fr;
                arw[im][0] = As_[m * A_STRIDE + k];
                arw[im][1] = As_[(m + 8) * A_STRIDE + k];
                arw[im][2] = As_[m * A_STRIDE + k + 4];
                arw[im][3] = As_[(m + 8) * A_STRIDE + k + 4];
            }
            float brw[8][2];
            #pragma unroll
            for (int jn = 0; jn < 8; jn++) {
                const int n = wn0 + jn * 8 + fr;
                brw[jn][0] = Bs_[k * 136 + n];
                brw[jn][1] = Bs_[(k + 4) * 136 + n];
            }
            // register-side hi/lo split
            uint32_t ah[4][4], al[4][4], bh[8][2], bl[8][2];
            #pragma unroll
            for (int im = 0; im < 4; im++)
                #pragma unroll
                for (int q = 0; q < 4; q++) {
                    float h = tf32r(arw[im][q]);
                    ah[im][q] = __float_as_uint(h);
                    if (NTERMS == 3) al[im][q] = __float_as_uint(arw[im][q] - h);
                }
            #pragma unroll
            for (int jn = 0; jn < 8; jn++)
                #pragma unroll
                for (int q = 0; q < 2; q++) {
                    float h = tf32r(brw[jn][q]);
                    bh[jn][q] = __float_as_uint(h);
                    bl[jn][q] = __float_as_uint(brw[jn][q] - h);
                }
            // MMA passes (independent accs back-to-back)
            #pragma unroll
            for (int im = 0; im < 4; im++)
                #pragma unroll
                for (int jn = 0; jn < 8; jn++)
                    mma_tf32(acc[im][jn], ah[im], bh[jn]);
            #pragma unroll
            for (int im = 0; im < 4; im++)
                #pragma unroll
                for (int jn = 0; jn < 8; jn++)
                    mma_tf32(acc[im][jn], ah[im], bl[jn]);
            if (NTERMS == 3) {
                #pragma unroll
                for (int im = 0; im < 4; im++)
                    #pragma unroll
                    for (int jn = 0; jn < 8; jn++)
                        mma_tf32(acc[im][jn], al[im], bh[jn]);
            }
        }

        if (kt + 2 < T) issue(kt + 2, (kt + 2) % NSTAGE);
        CPCOMMIT();
    }

    // ---- epilogue: bias + relu + store ----
    const float* bp = bias + sBiasE * e + n0;
    float* Cbase = C + sCe * e;
    #pragma unroll
    for (int im = 0; im < 4; im++) {
        #pragma unroll
        for (int half = 0; half < 2; half++) {
            const int rr = m0 + wm0 + im * 16 + (lane >> 2) + half * 8;
            if (rr < cnt) {
                float* crow = Cbase + (size_t)rr * N + n0;
                #pragma unroll
                for (int jn = 0; jn < 8; jn++) {
                    const int col = wn0 + jn * 8 + (lane & 3) * 2;
                    float v0 = acc[im][jn][half * 2 + 0] + bp[col];
                    float v1 = acc[im][jn][half * 2 + 1] + bp[col + 1];
                    if (doRelu) { v0 = fmaxf(v0, 0.f); v1 = fmaxf(v1, 0.f); }
                    *(float2*)(crow + col) = make_float2(v0, v1);
                }
            }
        }
    }
}

// ---------------- routing ----------------
__global__ void route_kernel(const float* __restrict__ h2,
                             const float* __restrict__ G3,
                             const float* __restrict__ g3,
                             float* __restrict__ pout)
{
    const int gw   = (blockIdx.x * blockDim.x + threadIdx.x) >> 5;
    const int lane = threadIdx.x & 31;
    if (gw >= NTOK) return;

    const float* hrow = h2 + (size_t)gw * DIN;
    float acc[8] = {0,0,0,0,0,0,0,0};
    for (int k = lane; k < DIN; k += 32) {
        float hv = hrow[k];
        const float4 ga = *(const float4*)(G3 + k * 8);
        const float4 gb = *(const float4*)(G3 + k * 8 + 4);
        acc[0] += hv * ga.x; acc[1] += hv * ga.y;
        acc[2] += hv * ga.z; acc[3] += hv * ga.w;
        acc[4] += hv * gb.x; acc[5] += hv * gb.y;
        acc[6] += hv * gb.z; acc[7] += hv * gb.w;
    }
    #pragma unroll
    for (int e = 0; e < 8; e++)
        #pragma unroll
        for (int o = 16; o; o >>= 1)
            acc[e] += __shfl_xor_sync(0xffffffffu, acc[e], o);

    if (lane == 0) {
        float lg[8];
        #pragma unroll
        for (int e = 0; e < 8; e++) lg[e] = acc[e] + g3[e];

        int i1 = 0; float v1 = lg[0];
        #pragma unroll
        for (int e = 1; e < 8; e++)
            if (lg[e] > v1) { v1 = lg[e]; i1 = e; }
        int i2 = -1; float v2 = -3.4e38f;
        #pragma unroll
        for (int e = 0; e < 8; e++)
            if (e != i1 && lg[e] > v2) { v2 = lg[e]; i2 = e; }

        float ex = expf(v2 - v1);
        float p1 = 1.f / (1.f + ex);
        float p2 = ex  / (1.f + ex);

        float pr[8] = {0,0,0,0,0,0,0,0};
        pr[i1] = p1; pr[i2] = p2;
        float* prow = pout + (size_t)gw * NEXP;
        *(float4*)prow       = make_float4(pr[0], pr[1], pr[2], pr[3]);
        *(float4*)(prow + 4) = make_float4(pr[4], pr[5], pr[6], pr[7]);

        int s1 = atomicAdd(&g_cnt[i1], 1);
        g_list[i1 * NTOK + s1] = gw;
        g_slot[gw * 2 + 0] = i1 * NTOK + s1;
        g_wt  [gw * 2 + 0] = p1;
        int s2 = atomicAdd(&g_cnt[i2], 1);
        g_list[i2 * NTOK + s2] = gw;
        g_slot[gw * 2 + 1] = i2 * NTOK + s2;
        g_wt  [gw * 2 + 1] = p2;
    }
}

// ---------------- combine ----------------
__global__ void combine_kernel(float* __restrict__ y)
{
    const int t = blockIdx.x;
    const int c = threadIdx.x * 4;
    const int s0 = g_slot[t * 2 + 0];
    const int s1 = g_slot[t * 2 + 1];
    const float w0 = g_wt[t * 2 + 0];
    const float w1 = g_wt[t * 2 + 1];
    float4 a = *(const float4*)(g_pout + (size_t)s0 * OUTD + c);
    float4 b = *(const float4*)(g_pout + (size_t)s1 * OUTD + c);
    float4 rr;
    rr.x = w0 * a.x + w1 * b.x;
    rr.y = w0 * a.y + w1 * b.y;
    rr.z = w0 * a.z + w1 * b.z;
    rr.w = w0 * a.w + w1 * b.w;
    *(float4*)(y + (size_t)t * OUTD + c) = rr;
}

// ---------------- launch ----------------
extern "C" void kernel_launch(void* const* d_in, const int* in_sizes, int n_in,
                              void* d_out, int out_size)
{
    const float* x  = (const float*)d_in[0];
    const float* W1 = (const float*)d_in[1];
    const float* b1 = (const float*)d_in[2];
    const float* W2 = (const float*)d_in[3];
    const float* b2 = (const float*)d_in[4];
    const float* G1 = (const float*)d_in[5];
    const float* g1 = (const float*)d_in[6];
    const float* G2 = (const float*)d_in[7];
    const float* g2 = (const float*)d_in[8];
    const float* G3 = (const float*)d_in[9];
    const float* g3 = (const float*)d_in[10];

    float* y = (float*)d_out;
    float* p = (float*)d_out + (size_t)NTOK * OUTD;

    void* tmp;
    cudaGetSymbolAddress(&tmp, g_h1);   float* h1  = (float*)tmp;
    cudaGetSymbolAddress(&tmp, g_h2);   float* h2  = (float*)tmp;
    cudaGetSymbolAddress(&tmp, g_hid);  float* hid = (float*)tmp;
    cudaGetSymbolAddress(&tmp, g_pout); float* po  = (float*)tmp;
    cudaGetSymbolAddress(&tmp, g_list); int*   lst = (int*)tmp;
    cudaGetSymbolAddress(&tmp, g_cnt);  int*   cnt = (int*)tmp;

    cudaFuncSetAttribute(gemm_tc<3>, cudaFuncAttributeMaxDynamicSharedMemorySize, SMEM_BYTES);
    cudaFuncSetAttribute(gemm_tc<2>, cudaFuncAttributeMaxDynamicSharedMemorySize, SMEM_BYTES);

    reset_kernel<<<1, 32>>>();

    // gate layer 1: h1 = relu(x @ G1 + g1)   — 3-term (selection-critical)
    gemm_tc<3><<<dim3(GH / 128, NTOK / 128, 1), 128, SMEM_BYTES>>>(
        x, 0, G1, 0, g1, 0, h1, 0, DIN, GH, 1, nullptr, nullptr);
    // gate layer 2: h2 = relu(h1 @ G2 + g2)  — 3-term
    gemm_tc<3><<<dim3(DIN / 128, NTOK / 128, 1), 128, SMEM_BYTES>>>(
        h1, 0, G2, 0, g2, 0, h2, 0, GH, DIN, 1, nullptr, nullptr);
    // routing
    route_kernel<<<NTOK / 8, 256>>>(h2, G3, g3, p);
    // expert FFN1: hid = relu(x[list] @ W1[e] + b1[e])  — 2-term
    gemm_tc<2><<<dim3(HID / 128, NTOK / 128, NEXP), 128, SMEM_BYTES>>>(
        x, 0, W1, (size_t)DIN * HID, b1, HID, hid, (size_t)NTOK * HID,
        DIN, HID, 1, lst, cnt);
    // expert FFN2: pout = hid @ W2[e] + b2[e]  — 2-term
    gemm_tc<2><<<dim3(OUTD / 128, NTOK / 128, NEXP), 128, SMEM_BYTES>>>(
        hid, (size_t)NTOK * HID, W2, (size_t)HID * OUTD, b2, OUTD, po, (size_t)NTOK * OUTD,
        HID, OUTD, 0, nullptr, cnt);
    // combine
    combine_kernel<<<NTOK, 256>>>(y);
}

// round 6
// speedup vs baseline: 1.8559x; 1.1298x over previous
#include <cuda_runtime.h>
#include <math.h>
#include <stdint.h>

#define NTOK 8192
#define DIN  1024
#define NEXP 8
#define HID  4096
#define OUTD 1024
#define GH   4096

// ---------------- scratch ----------------
__device__ float g_h1 [(size_t)NTOK * GH];
__device__ float g_h2 [(size_t)NTOK * DIN];
__device__ float g_hid [(size_t)NEXP * NTOK * HID];
__device__ float g_pout[(size_t)NEXP * NTOK * OUTD];
__device__ int   g_cnt [NEXP];
__device__ int   g_list[NEXP * NTOK];
__device__ int   g_slot[NTOK * 2];
__device__ float g_wt  [NTOK * 2];

__device__ __forceinline__ float tf32r(float x) {
    float r; asm("cvt.rna.tf32.f32 %0, %1;" : "=f"(r) : "f"(x)); return r;
}
__device__ __forceinline__ uint32_t cvta_s(const void* p) {
    uint32_t a;
    asm("{ .reg .u64 t; cvta.to.shared.u64 t, %1; cvt.u32.u64 %0, t; }" : "=r"(a) : "l"(p));
    return a;
}
#define CP16(d, s)  asm volatile("cp.async.ca.shared.global [%0], [%1], 16;" :: "r"(d), "l"(s))
#define CPCOMMIT()  asm volatile("cp.async.commit_group;" ::: "memory")
#define CPWAIT1()   asm volatile("cp.async.wait_group 1;" ::: "memory")

__device__ __forceinline__ void mma_tf32(float* c, const uint32_t* a, const uint32_t* b) {
    asm volatile(
        "mma.sync.aligned.m16n8k8.row.col.f32.tf32.tf32.f32 "
        "{%0,%1,%2,%3}, {%4,%5,%6,%7}, {%8,%9}, {%0,%1,%2,%3};\n"
        : "+f"(c[0]), "+f"(c[1]), "+f"(c[2]), "+f"(c[3])
        : "r"(a[0]), "r"(a[1]), "r"(a[2]), "r"(a[3]), "r"(b[0]), "r"(b[1]));
}

// SMEM per stage: A raw [128 rows][20 floats] (conflict-free), B raw [16 k][136 n]
#define A_STRIDE 20
#define A_PLANE  (128 * A_STRIDE)          // 2560 floats
#define B_PLANE  (16 * 136)                // 2176 floats
#define STAGE_F  (A_PLANE + B_PLANE)       // 4736 floats
#define NSTAGE   3
#define SMEM_BYTES (NSTAGE * STAGE_F * 4)  // 56832

// ---------------- reset ----------------
__global__ void reset_kernel() {
    if (threadIdx.x < NEXP) g_cnt[threadIdx.x] = 0;
}

// ---------------- NTERMS x TF32 GEMM: C = (A @ B + bias)[relu], B row-major [K,N] ----------------
// 256 threads, 8 warps, warp tile 64x32 (warp grid 2m x 4n), CTA tile 128x128, BK=16.
template<int NTERMS>
__global__ __launch_bounds__(256) void gemm_tc(
    const float* __restrict__ A, size_t sAe,
    const float* __restrict__ B, size_t sBe,
    const float* __restrict__ bias, size_t sBiasE,
    float* __restrict__ C, size_t sCe,
    int K, int N, int doRelu,
    const int* __restrict__ list, const int* __restrict__ cntArr)
{
    const int e   = blockIdx.z;
    const int cnt = cntArr ? cntArr[e] : (int)(gridDim.y * 128);
    const int m0  = blockIdx.y * 128;
    if (m0 >= cnt) return;
    const int n0  = blockIdx.x * 128;

    extern __shared__ float smem[];
    const uint32_t sbase = cvta_s(smem);

    const int tid  = threadIdx.x;
    const int wid  = tid >> 5;
    const int lane = tid & 31;
    const int wm0  = (wid >> 2) * 64;   // 2 m-warps
    const int wn0  = (wid & 3) * 32;    // 4 n-warps

    // loaders: A row = tid>>1, 8 floats per thread; B: bk = tid>>4, 8 floats
    int arow = m0 + (tid >> 1); if (arow > cnt - 1) arow = cnt - 1;
    if (list) arow = list[e * NTOK + arow];
    const int acol = (tid & 1) * 8;
    const float* Ap = A + sAe * e + (size_t)arow * K + acol;
    const int bk = tid >> 4;
    const int bn = (tid & 15) * 8;
    const float* Bp = B + sBe * e + (size_t)bk * N + n0 + bn;
    const uint32_t adst0 = sbase + (uint32_t)((tid >> 1) * A_STRIDE + acol) * 4u;
    const uint32_t bdst0 = sbase + (uint32_t)(A_PLANE + bk * 136 + bn) * 4u;

    const int T = K >> 4;

    auto issue = [&](int kt, int s) {
        const float* ap = Ap + kt * 16;
        uint32_t ad = adst0 + (uint32_t)(s * STAGE_F) * 4u;
        CP16(ad,      ap);
        CP16(ad + 16, ap + 4);
        const float* bp = Bp + (size_t)kt * 16 * N;
        uint32_t bd = bdst0 + (uint32_t)(s * STAGE_F) * 4u;
        CP16(bd,      bp);
        CP16(bd + 16, bp + 4);
    };

    float acc[4][4][4];
    #pragma unroll
    for (int im = 0; im < 4; im++)
        #pragma unroll
        for (int jn = 0; jn < 4; jn++)
            #pragma unroll
            for (int q = 0; q < 4; q++) acc[im][jn][q] = 0.f;

    issue(0, 0); CPCOMMIT();
    if (T > 1) issue(1, 1);
    CPCOMMIT();

    const int fr = lane >> 2;
    const int fk = lane & 3;

    for (int kt = 0; kt < T; ++kt) {
        CPWAIT1();
        __syncthreads();
        const int s = kt % NSTAGE;
        const float* As_ = smem + s * STAGE_F;
        const float* Bs_ = smem + s * STAGE_F + A_PLANE;

        #pragma unroll
        for (int ks = 0; ks < 16; ks += 8) {
            const int k = ks + fk;
            float arw[4][4];
            #pragma unroll
            for (int im = 0; im < 4; im++) {
                const int m = wm0 + im * 16 + fr;
                arw[im][0] = As_[m * A_STRIDE + k];
                arw[im][1] = As_[(m + 8) * A_STRIDE + k];
                arw[im][2] = As_[m * A_STRIDE + k + 4];
                arw[im][3] = As_[(m + 8) * A_STRIDE + k + 4];
            }
            float brw[4][2];
            #pragma unroll
            for (int jn = 0; jn < 4; jn++) {
                const int n = wn0 + jn * 8 + fr;
                brw[jn][0] = Bs_[k * 136 + n];
                brw[jn][1] = Bs_[(k + 4) * 136 + n];
            }
            uint32_t ah[4][4], al[4][4], bh[4][2], bl[4][2];
            #pragma unroll
            for (int im = 0; im < 4; im++)
                #pragma unroll
                for (int q = 0; q < 4; q++) {
                    float h = tf32r(arw[im][q]);
                    ah[im][q] = __float_as_uint(h);
                    if (NTERMS == 3) al[im][q] = __float_as_uint(arw[im][q] - h);
                }
            #pragma unroll
            for (int jn = 0; jn < 4; jn++)
                #pragma unroll
                for (int q = 0; q < 2; q++) {
                    float h = tf32r(brw[jn][q]);
                    bh[jn][q] = __float_as_uint(h);
                    bl[jn][q] = __float_as_uint(brw[jn][q] - h);
                }
            #pragma unroll
            for (int im = 0; im < 4; im++)
                #pragma unroll
                for (int jn = 0; jn < 4; jn++)
                    mma_tf32(acc[im][jn], ah[im], bh[jn]);
            #pragma unroll
            for (int im = 0; im < 4; im++)
                #pragma unroll
                for (int jn = 0; jn < 4; jn++)
                    mma_tf32(acc[im][jn], ah[im], bl[jn]);
            if (NTERMS == 3) {
                #pragma unroll
                for (int im = 0; im < 4; im++)
                    #pragma unroll
                    for (int jn = 0; jn < 4; jn++)
                        mma_tf32(acc[im][jn], al[im], bh[jn]);
            }
        }

        if (kt + 2 < T) issue(kt + 2, (kt + 2) % NSTAGE);
        CPCOMMIT();
    }

    // ---- epilogue: bias + relu + store ----
    const float* bp = bias + sBiasE * e + n0;
    float* Cbase = C + sCe * e;
    #pragma unroll
    for (int im = 0; im < 4; im++) {
        #pragma unroll
        for (int half = 0; half < 2; half++) {
            const int rr = m0 + wm0 + im * 16 + (lane >> 2) + half * 8;
            if (rr < cnt) {
                float* crow = Cbase + (size_t)rr * N + n0;
                #pragma unroll
                for (int jn = 0; jn < 4; jn++) {
                    const int col = wn0 + jn * 8 + (lane & 3) * 2;
                    float v0 = acc[im][jn][half * 2 + 0] + bp[col];
                    float v1 = acc[im][jn][half * 2 + 1] + bp[col + 1];
                    if (doRelu) { v0 = fmaxf(v0, 0.f); v1 = fmaxf(v1, 0.f); }
                    *(float2*)(crow + col) = make_float2(v0, v1);
                }
            }
        }
    }
}

// ---------------- routing ----------------
__global__ void route_kernel(const float* __restrict__ h2,
                             const float* __restrict__ G3,
                             const float* __restrict__ g3,
                             float* __restrict__ pout)
{
    const int gw   = (blockIdx.x * blockDim.x + threadIdx.x) >> 5;
    const int lane = threadIdx.x & 31;
    if (gw >= NTOK) return;

    const float* hrow = h2 + (size_t)gw * DIN;
    float acc[8] = {0,0,0,0,0,0,0,0};
    for (int k = lane; k < DIN; k += 32) {
        float hv = hrow[k];
        const float4 ga = *(const float4*)(G3 + k * 8);
        const float4 gb = *(const float4*)(G3 + k * 8 + 4);
        acc[0] += hv * ga.x; acc[1] += hv * ga.y;
        acc[2] += hv * ga.z; acc[3] += hv * ga.w;
        acc[4] += hv * gb.x; acc[5] += hv * gb.y;
        acc[6] += hv * gb.z; acc[7] += hv * gb.w;
    }
    #pragma unroll
    for (int e = 0; e < 8; e++)
        #pragma unroll
        for (int o = 16; o; o >>= 1)
            acc[e] += __shfl_xor_sync(0xffffffffu, acc[e], o);

    if (lane == 0) {
        float lg[8];
        #pragma unroll
        for (int e = 0; e < 8; e++) lg[e] = acc[e] + g3[e];

        int i1 = 0; float v1 = lg[0];
        #pragma unroll
        for (int e = 1; e < 8; e++)
            if (lg[e] > v1) { v1 = lg[e]; i1 = e; }
        int i2 = -1; float v2 = -3.4e38f;
        #pragma unroll
        for (int e = 0; e < 8; e++)
            if (e != i1 && lg[e] > v2) { v2 = lg[e]; i2 = e; }

        float ex = expf(v2 - v1);
        float p1 = 1.f / (1.f + ex);
        float p2 = ex  / (1.f + ex);

        float pr[8] = {0,0,0,0,0,0,0,0};
        pr[i1] = p1; pr[i2] = p2;
        float* prow = pout + (size_t)gw * NEXP;
        *(float4*)prow       = make_float4(pr[0], pr[1], pr[2], pr[3]);
        *(float4*)(prow + 4) = make_float4(pr[4], pr[5], pr[6], pr[7]);

        int s1 = atomicAdd(&g_cnt[i1], 1);
        g_list[i1 * NTOK + s1] = gw;
        g_slot[gw * 2 + 0] = i1 * NTOK + s1;
        g_wt  [gw * 2 + 0] = p1;
        int s2 = atomicAdd(&g_cnt[i2], 1);
        g_list[i2 * NTOK + s2] = gw;
        g_slot[gw * 2 + 1] = i2 * NTOK + s2;
        g_wt  [gw * 2 + 1] = p2;
    }
}

// ---------------- combine ----------------
__global__ void combine_kernel(float* __restrict__ y)
{
    const int t = blockIdx.x;
    const int c = threadIdx.x * 4;
    const int s0 = g_slot[t * 2 + 0];
    const int s1 = g_slot[t * 2 + 1];
    const float w0 = g_wt[t * 2 + 0];
    const float w1 = g_wt[t * 2 + 1];
    float4 a = *(const float4*)(g_pout + (size_t)s0 * OUTD + c);
    float4 b = *(const float4*)(g_pout + (size_t)s1 * OUTD + c);
    float4 rr;
    rr.x = w0 * a.x + w1 * b.x;
    rr.y = w0 * a.y + w1 * b.y;
    rr.z = w0 * a.z + w1 * b.z;
    rr.w = w0 * a.w + w1 * b.w;
    *(float4*)(y + (size_t)t * OUTD + c) = rr;
}

// ---------------- launch ----------------
extern "C" void kernel_launch(void* const* d_in, const int* in_sizes, int n_in,
                              void* d_out, int out_size)
{
    const float* x  = (const float*)d_in[0];
    const float* W1 = (const float*)d_in[1];
    const float* b1 = (const float*)d_in[2];
    const float* W2 = (const float*)d_in[3];
    const float* b2 = (const float*)d_in[4];
    const float* G1 = (const float*)d_in[5];
    const float* g1 = (const float*)d_in[6];
    const float* G2 = (const float*)d_in[7];
    const float* g2 = (const float*)d_in[8];
    const float* G3 = (const float*)d_in[9];
    const float* g3 = (const float*)d_in[10];

    float* y = (float*)d_out;
    float* p = (float*)d_out + (size_t)NTOK * OUTD;

    void* tmp;
    cudaGetSymbolAddress(&tmp, g_h1);   float* h1  = (float*)tmp;
    cudaGetSymbolAddress(&tmp, g_h2);   float* h2  = (float*)tmp;
    cudaGetSymbolAddress(&tmp, g_hid);  float* hid = (float*)tmp;
    cudaGetSymbolAddress(&tmp, g_pout); float* po  = (float*)tmp;
    cudaGetSymbolAddress(&tmp, g_list); int*   lst = (int*)tmp;
    cudaGetSymbolAddress(&tmp, g_cnt);  int*   cnt = (int*)tmp;

    cudaFuncSetAttribute(gemm_tc<3>, cudaFuncAttributeMaxDynamicSharedMemorySize, SMEM_BYTES);
    cudaFuncSetAttribute(gemm_tc<2>, cudaFuncAttributeMaxDynamicSharedMemorySize, SMEM_BYTES);

    reset_kernel<<<1, 32>>>();

    // gate layer 1: h1 = relu(x @ G1 + g1)   — 3-term (selection-critical)
    gemm_tc<3><<<dim3(GH / 128, NTOK / 128, 1), 256, SMEM_BYTES>>>(
        x, 0, G1, 0, g1, 0, h1, 0, DIN, GH, 1, nullptr, nullptr);
    // gate layer 2: h2 = relu(h1 @ G2 + g2)  — 3-term
    gemm_tc<3><<<dim3(DIN / 128, NTOK / 128, 1), 256, SMEM_BYTES>>>(
        h1, 0, G2, 0, g2, 0, h2, 0, GH, DIN, 1, nullptr, nullptr);
    // routing
    route_kernel<<<NTOK / 8, 256>>>(h2, G3, g3, p);
    // expert FFN1: hid = relu(x[list] @ W1[e] + b1[e])  — 2-term
    gemm_tc<2><<<dim3(HID / 128, NTOK / 128, NEXP), 256, SMEM_BYTES>>>(
        x, 0, W1, (size_t)DIN * HID, b1, HID, hid, (size_t)NTOK * HID,
        DIN, HID, 1, lst, cnt);
    // expert FFN2: pout = hid @ W2[e] + b2[e]  — 2-term
    gemm_tc<2><<<dim3(OUTD / 128, NTOK / 128, NEXP), 256, SMEM_BYTES>>>(
        hid, (size_t)NTOK * HID, W2, (size_t)HID * OUTD, b2, OUTD, po, (size_t)NTOK * OUTD,
        HID, OUTD, 0, nullptr, cnt);
    // combine
    combine_kernel<<<NTOK, 256>>>(y);
}

// round 7
// speedup vs baseline: 2.0595x; 1.1097x over previous
#include <cuda_runtime.h>
#include <math.h>
#include <stdint.h>

#define NTOK 8192
#define DIN  1024
#define NEXP 8
#define HID  4096
#define OUTD 1024
#define GH   4096

// ---------------- scratch ----------------
__device__ float g_h1 [(size_t)NTOK * GH];
__device__ float g_h2 [(size_t)NTOK * DIN];
__device__ float g_hid [(size_t)NEXP * NTOK * HID];
__device__ float g_pout[(size_t)NEXP * NTOK * OUTD];
__device__ int   g_cnt [NEXP];
__device__ int   g_list[NEXP * NTOK];
__device__ int   g_slot[NTOK * 2];
__device__ float g_wt  [NTOK * 2];

__device__ __forceinline__ float tf32r(float x) {
    float r; asm("cvt.rna.tf32.f32 %0, %1;" : "=f"(r) : "f"(x)); return r;
}
__device__ __forceinline__ uint32_t cvta_s(const void* p) {
    uint32_t a;
    asm("{ .reg .u64 t; cvta.to.shared.u64 t, %1; cvt.u32.u64 %0, t; }" : "=r"(a) : "l"(p));
    return a;
}
#define CP16(d, s)  asm volatile("cp.async.ca.shared.global [%0], [%1], 16;" :: "r"(d), "l"(s))
#define CPCOMMIT()  asm volatile("cp.async.commit_group;" ::: "memory")
#define CPWAIT1()   asm volatile("cp.async.wait_group 1;" ::: "memory")

__device__ __forceinline__ void mma_tf32(float* c, const uint32_t* a, const uint32_t* b) {
    asm volatile(
        "mma.sync.aligned.m16n8k8.row.col.f32.tf32.tf32.f32 "
        "{%0,%1,%2,%3}, {%4,%5,%6,%7}, {%8,%9}, {%0,%1,%2,%3};\n"
        : "+f"(c[0]), "+f"(c[1]), "+f"(c[2]), "+f"(c[3])
        : "r"(a[0]), "r"(a[1]), "r"(a[2]), "r"(a[3]), "r"(b[0]), "r"(b[1]));
}
__device__ __forceinline__ void mma_bf16(float* c, const uint32_t* a, const uint32_t* b) {
    asm volatile(
        "mma.sync.aligned.m16n8k16.row.col.f32.bf16.bf16.f32 "
        "{%0,%1,%2,%3}, {%4,%5,%6,%7}, {%8,%9}, {%0,%1,%2,%3};\n"
        : "+f"(c[0]), "+f"(c[1]), "+f"(c[2]), "+f"(c[3])
        : "r"(a[0]), "r"(a[1]), "r"(a[2]), "r"(a[3]), "r"(b[0]), "r"(b[1]));
}

// exact 2-way bf16 split of a pair: hi = trunc16(v), mid = trunc16(v - hi); packed (lo=x, hi=y)
__device__ __forceinline__ void split2(float x, float y, uint32_t& hi, uint32_t& mid) {
    uint32_t ux = __float_as_uint(x), uy = __float_as_uint(y);
    hi = __byte_perm(ux, uy, 0x7632);
    float rx = x - __uint_as_float(ux & 0xFFFF0000u);
    float ry = y - __uint_as_float(uy & 0xFFFF0000u);
    mid = __byte_perm(__float_as_uint(rx), __float_as_uint(ry), 0x7632);
}

// SMEM per stage: A raw [128 rows][20 floats], B raw [16 k][BSTR n]
#define A_STRIDE 20
#define A_PLANE  (128 * A_STRIDE)          // 2560 floats
#define STAGE_F  (A_PLANE + 16 * 136)      // max of both modes: 4736 floats
#define NSTAGE   3
#define SMEM_BYTES (NSTAGE * STAGE_F * 4)  // 56832

// ---------------- reset ----------------
__global__ void reset_kernel() {
    if (threadIdx.x < NEXP) g_cnt[threadIdx.x] = 0;
}

// ---------------- GEMM: C = (A @ B + bias)[relu], B row-major [K,N] ----------------
// MODE 0: tf32 3-term (gates).  MODE 1: bf16 2-split 3-MMA (experts).
// 256 threads, 8 warps, warp tile 64x32 (2m x 4n warps), CTA tile 128x128, BK=16.
template<int MODE>
__global__ __launch_bounds__(256) void gemm_tc(
    const float* __restrict__ A, size_t sAe,
    const float* __restrict__ B, size_t sBe,
    const float* __restrict__ bias, size_t sBiasE,
    float* __restrict__ C, size_t sCe,
    int K, int N, int doRelu,
    const int* __restrict__ list, const int* __restrict__ cntArr)
{
    const int BSTR = MODE ? 132 : 136;   // conflict-free B stride per fragment pattern
    const int e   = blockIdx.z;
    const int cnt = cntArr ? cntArr[e] : (int)(gridDim.y * 128);
    const int m0  = blockIdx.y * 128;
    if (m0 >= cnt) return;
    const int n0  = blockIdx.x * 128;

    extern __shared__ float smem[];
    const uint32_t sbase = cvta_s(smem);

    const int tid  = threadIdx.x;
    const int wid  = tid >> 5;
    const int lane = tid & 31;
    const int wm0  = (wid >> 2) * 64;
    const int wn0  = (wid & 3) * 32;

    int arow = m0 + (tid >> 1); if (arow > cnt - 1) arow = cnt - 1;
    if (list) arow = list[e * NTOK + arow];
    const int acol = (tid & 1) * 8;
    const float* Ap = A + sAe * e + (size_t)arow * K + acol;
    const int bk = tid >> 4;
    const int bn = (tid & 15) * 8;
    const float* Bp = B + sBe * e + (size_t)bk * N + n0 + bn;
    const uint32_t adst0 = sbase + (uint32_t)((tid >> 1) * A_STRIDE + acol) * 4u;
    const uint32_t bdst0 = sbase + (uint32_t)(A_PLANE + bk * BSTR + bn) * 4u;

    const int T = K >> 4;

    auto issue = [&](int kt, int s) {
        const float* ap = Ap + kt * 16;
        uint32_t ad = adst0 + (uint32_t)(s * STAGE_F) * 4u;
        CP16(ad,      ap);
        CP16(ad + 16, ap + 4);
        const float* bp = Bp + (size_t)kt * 16 * N;
        uint32_t bd = bdst0 + (uint32_t)(s * STAGE_F) * 4u;
        CP16(bd,      bp);
        CP16(bd + 16, bp + 4);
    };

    float acc[4][4][4];
    #pragma unroll
    for (int im = 0; im < 4; im++)
        #pragma unroll
        for (int jn = 0; jn < 4; jn++)
            #pragma unroll
            for (int q = 0; q < 4; q++) acc[im][jn][q] = 0.f;

    issue(0, 0); CPCOMMIT();
    if (T > 1) issue(1, 1);
    CPCOMMIT();

    const int fr = lane >> 2;
    const int fk = lane & 3;

    for (int kt = 0; kt < T; ++kt) {
        CPWAIT1();
        __syncthreads();
        const int s = kt % NSTAGE;
        const float* As_ = smem + s * STAGE_F;
        const float* Bs_ = smem + s * STAGE_F + A_PLANE;

        if (MODE == 1) {
            // ---- bf16 2-split, 3 x m16n8k16 over the whole k16 chunk ----
            const int k2 = fk * 2;
            uint32_t ah[4][4], am[4][4];
            #pragma unroll
            for (int im = 0; im < 4; im++) {
                const int m = wm0 + im * 16 + fr;
                float2 v00 = *(const float2*)&As_[m * A_STRIDE + k2];
                float2 v10 = *(const float2*)&As_[(m + 8) * A_STRIDE + k2];
                float2 v01 = *(const float2*)&As_[m * A_STRIDE + k2 + 8];
                float2 v11 = *(const float2*)&As_[(m + 8) * A_STRIDE + k2 + 8];
                split2(v00.x, v00.y, ah[im][0], am[im][0]);
                split2(v10.x, v10.y, ah[im][1], am[im][1]);
                split2(v01.x, v01.y, ah[im][2], am[im][2]);
                split2(v11.x, v11.y, ah[im][3], am[im][3]);
            }
            uint32_t bh[4][2], bm[4][2];
            #pragma unroll
            for (int jn = 0; jn < 4; jn++) {
                const int n = wn0 + jn * 8 + fr;
                float b0 = Bs_[(k2)     * BSTR + n];
                float b1 = Bs_[(k2 + 1) * BSTR + n];
                float b2 = Bs_[(k2 + 8) * BSTR + n];
                float b3 = Bs_[(k2 + 9) * BSTR + n];
                split2(b0, b1, bh[jn][0], bm[jn][0]);
                split2(b2, b3, bh[jn][1], bm[jn][1]);
            }
            #pragma unroll
            for (int im = 0; im < 4; im++)
                #pragma unroll
                for (int jn = 0; jn < 4; jn++)
                    mma_bf16(acc[im][jn], ah[im], bh[jn]);
            #pragma unroll
            for (int im = 0; im < 4; im++)
                #pragma unroll
                for (int jn = 0; jn < 4; jn++)
                    mma_bf16(acc[im][jn], ah[im], bm[jn]);
            #pragma unroll
            for (int im = 0; im < 4; im++)
                #pragma unroll
                for (int jn = 0; jn < 4; jn++)
                    mma_bf16(acc[im][jn], am[im], bh[jn]);
        } else {
            // ---- tf32 3-term, 2 x k8 steps ----
            #pragma unroll
            for (int ks = 0; ks < 16; ks += 8) {
                const int k = ks + fk;
                float arw[4][4];
                #pragma unroll
                for (int im = 0; im < 4; im++) {
                    const int m = wm0 + im * 16 + fr;
                    arw[im][0] = As_[m * A_STRIDE + k];
                    arw[im][1] = As_[(m + 8) * A_STRIDE + k];
                    arw[im][2] = As_[m * A_STRIDE + k + 4];
                    arw[im][3] = As_[(m + 8) * A_STRIDE + k + 4];
                }
                float brw[4][2];
                #pragma unroll
                for (int jn = 0; jn < 4; jn++) {
                    const int n = wn0 + jn * 8 + fr;
                    brw[jn][0] = Bs_[k * BSTR + n];
                    brw[jn][1] = Bs_[(k + 4) * BSTR + n];
                }
                uint32_t ah[4][4], al[4][4], bh[4][2], bl[4][2];
                #pragma unroll
                for (int im = 0; im < 4; im++)
                    #pragma unroll
                    for (int q = 0; q < 4; q++) {
                        float h = tf32r(arw[im][q]);
                        ah[im][q] = __float_as_uint(h);
                        al[im][q] = __float_as_uint(arw[im][q] - h);
                    }
                #pragma unroll
                for (int jn = 0; jn < 4; jn++)
                    #pragma unroll
                    for (int q = 0; q < 2; q++) {
                        float h = tf32r(brw[jn][q]);
                        bh[jn][q] = __float_as_uint(h);
                        bl[jn][q] = __float_as_uint(brw[jn][q] - h);
                    }
                #pragma unroll
                for (int im = 0; im < 4; im++)
                    #pragma unroll
                    for (int jn = 0; jn < 4; jn++)
                        mma_tf32(acc[im][jn], ah[im], bh[jn]);
                #pragma unroll
                for (int im = 0; im < 4; im++)
                    #pragma unroll
                    for (int jn = 0; jn < 4; jn++)
                        mma_tf32(acc[im][jn], ah[im], bl[jn]);
                #pragma unroll
                for (int im = 0; im < 4; im++)
                    #pragma unroll
                    for (int jn = 0; jn < 4; jn++)
                        mma_tf32(acc[im][jn], al[im], bh[jn]);
            }
        }

        if (kt + 2 < T) issue(kt + 2, (kt + 2) % NSTAGE);
        CPCOMMIT();
    }

    // ---- epilogue: bias + relu + store ----
    const float* bp = bias + sBiasE * e + n0;
    float* Cbase = C + sCe * e;
    #pragma unroll
    for (int im = 0; im < 4; im++) {
        #pragma unroll
        for (int half = 0; half < 2; half++) {
            const int rr = m0 + wm0 + im * 16 + (lane >> 2) + half * 8;
            if (rr < cnt) {
                float* crow = Cbase + (size_t)rr * N + n0;
                #pragma unroll
                for (int jn = 0; jn < 4; jn++) {
                    const int col = wn0 + jn * 8 + (lane & 3) * 2;
                    float v0 = acc[im][jn][half * 2 + 0] + bp[col];
                    float v1 = acc[im][jn][half * 2 + 1] + bp[col + 1];
                    if (doRelu) { v0 = fmaxf(v0, 0.f); v1 = fmaxf(v1, 0.f); }
                    *(float2*)(crow + col) = make_float2(v0, v1);
                }
            }
        }
    }
}

// ---------------- routing ----------------
__global__ void route_kernel(const float* __restrict__ h2,
                             const float* __restrict__ G3,
                             const float* __restrict__ g3,
                             float* __restrict__ pout)
{
    const int gw   = (blockIdx.x * blockDim.x + threadIdx.x) >> 5;
    const int lane = threadIdx.x & 31;
    if (gw >= NTOK) return;

    const float* hrow = h2 + (size_t)gw * DIN;
    float acc[8] = {0,0,0,0,0,0,0,0};
    for (int k = lane; k < DIN; k += 32) {
        float hv = hrow[k];
        const float4 ga = *(const float4*)(G3 + k * 8);
        const float4 gb = *(const float4*)(G3 + k * 8 + 4);
        acc[0] += hv * ga.x; acc[1] += hv * ga.y;
        acc[2] += hv * ga.z; acc[3] += hv * ga.w;
        acc[4] += hv * gb.x; acc[5] += hv * gb.y;
        acc[6] += hv * gb.z; acc[7] += hv * gb.w;
    }
    #pragma unroll
    for (int e = 0; e < 8; e++)
        #pragma unroll
        for (int o = 16; o; o >>= 1)
            acc[e] += __shfl_xor_sync(0xffffffffu, acc[e], o);

    if (lane == 0) {
        float lg[8];
        #pragma unroll
        for (int e = 0; e < 8; e++) lg[e] = acc[e] + g3[e];

        int i1 = 0; float v1 = lg[0];
        #pragma unroll
        for (int e = 1; e < 8; e++)
            if (lg[e] > v1) { v1 = lg[e]; i1 = e; }
        int i2 = -1; float v2 = -3.4e38f;
        #pragma unroll
        for (int e = 0; e < 8; e++)
            if (e != i1 && lg[e] > v2) { v2 = lg[e]; i2 = e; }

        float ex = expf(v2 - v1);
        float p1 = 1.f / (1.f + ex);
        float p2 = ex  / (1.f + ex);

        float pr[8] = {0,0,0,0,0,0,0,0};
        pr[i1] = p1; pr[i2] = p2;
        float* prow = pout + (size_t)gw * NEXP;
        *(float4*)prow       = make_float4(pr[0], pr[1], pr[2], pr[3]);
        *(float4*)(prow + 4) = make_float4(pr[4], pr[5], pr[6], pr[7]);

        int s1 = atomicAdd(&g_cnt[i1], 1);
        g_list[i1 * NTOK + s1] = gw;
        g_slot[gw * 2 + 0] = i1 * NTOK + s1;
        g_wt  [gw * 2 + 0] = p1;
        int s2 = atomicAdd(&g_cnt[i2], 1);
        g_list[i2 * NTOK + s2] = gw;
        g_slot[gw * 2 + 1] = i2 * NTOK + s2;
        g_wt  [gw * 2 + 1] = p2;
    }
}

// ---------------- combine ----------------
__global__ void combine_kernel(float* __restrict__ y)
{
    const int t = blockIdx.x;
    const int c = threadIdx.x * 4;
    const int s0 = g_slot[t * 2 + 0];
    const int s1 = g_slot[t * 2 + 1];
    const float w0 = g_wt[t * 2 + 0];
    const float w1 = g_wt[t * 2 + 1];
    float4 a = *(const float4*)(g_pout + (size_t)s0 * OUTD + c);
    float4 b = *(const float4*)(g_pout + (size_t)s1 * OUTD + c);
    float4 rr;
    rr.x = w0 * a.x + w1 * b.x;
    rr.y = w0 * a.y + w1 * b.y;
    rr.z = w0 * a.z + w1 * b.z;
    rr.w = w0 * a.w + w1 * b.w;
    *(float4*)(y + (size_t)t * OUTD + c) = rr;
}

// ---------------- launch ----------------
extern "C" void kernel_launch(void* const* d_in, const int* in_sizes, int n_in,
                              void* d_out, int out_size)
{
    const float* x  = (const float*)d_in[0];
    const float* W1 = (const float*)d_in[1];
    const float* b1 = (const float*)d_in[2];
    const float* W2 = (const float*)d_in[3];
    const float* b2 = (const float*)d_in[4];
    const float* G1 = (const float*)d_in[5];
    const float* g1 = (const float*)d_in[6];
    const float* G2 = (const float*)d_in[7];
    const float* g2 = (const float*)d_in[8];
    const float* G3 = (const float*)d_in[9];
    const float* g3 = (const float*)d_in[10];

    float* y = (float*)d_out;
    float* p = (float*)d_out + (size_t)NTOK * OUTD;

    void* tmp;
    cudaGetSymbolAddress(&tmp, g_h1);   float* h1  = (float*)tmp;
    cudaGetSymbolAddress(&tmp, g_h2);   float* h2  = (float*)tmp;
    cudaGetSymbolAddress(&tmp, g_hid);  float* hid = (float*)tmp;
    cudaGetSymbolAddress(&tmp, g_pout); float* po  = (float*)tmp;
    cudaGetSymbolAddress(&tmp, g_list); int*   lst = (int*)tmp;
    cudaGetSymbolAddress(&tmp, g_cnt);  int*   cnt = (int*)tmp;

    cudaFuncSetAttribute(gemm_tc<0>, cudaFuncAttributeMaxDynamicSharedMemorySize, SMEM_BYTES);
    cudaFuncSetAttribute(gemm_tc<1>, cudaFuncAttributeMaxDynamicSharedMemorySize, SMEM_BYTES);

    reset_kernel<<<1, 32>>>();

    // gate layer 1: h1 = relu(x @ G1 + g1)   — tf32 3-term (selection-critical)
    gemm_tc<0><<<dim3(GH / 128, NTOK / 128, 1), 256, SMEM_BYTES>>>(
        x, 0, G1, 0, g1, 0, h1, 0, DIN, GH, 1, nullptr, nullptr);
    // gate layer 2: h2 = relu(h1 @ G2 + g2)  — tf32 3-term
    gemm_tc<0><<<dim3(DIN / 128, NTOK / 128, 1), 256, SMEM_BYTES>>>(
        h1, 0, G2, 0, g2, 0, h2, 0, GH, DIN, 1, nullptr, nullptr);
    // routing
    route_kernel<<<NTOK / 8, 256>>>(h2, G3, g3, p);
    // expert FFN1: hid = relu(x[list] @ W1[e] + b1[e])  — bf16 3-MMA
    gemm_tc<1><<<dim3(HID / 128, NTOK / 128, NEXP), 256, SMEM_BYTES>>>(
        x, 0, W1, (size_t)DIN * HID, b1, HID, hid, (size_t)NTOK * HID,
        DIN, HID, 1, lst, cnt);
    // expert FFN2: pout = hid @ W2[e] + b2[e]  — bf16 3-MMA
    gemm_tc<1><<<dim3(OUTD / 128, NTOK / 128, NEXP), 256, SMEM_BYTES>>>(
        hid, (size_t)NTOK * HID, W2, (size_t)HID * OUTD, b2, OUTD, po, (size_t)NTOK * OUTD,
        HID, OUTD, 0, nullptr, cnt);
    // combine
    combine_kernel<<<NTOK, 256>>>(y);
}